// round 5
// baseline (speedup 1.0000x reference)
#include <cuda_runtime.h>

// ---------------------------------------------------------------------------
// GCN 5-layer forward, max-aggregation (GB300).
//  y_l = dinv ⊙ (h_{l-1} @ W_l)  (pow2-padded rows)
//  h_l[c] = tanh( dinv[c] * max(y_l[c], y_l[nbrs]) + b_l )
//  Aggregation: lanes own float4/float2 feature chunks; next-layer GEMM fused
//  into epilogue. Nodes processed in degree-sorted order (counting sort) so
//  warp groups have equal trip counts -> no divergence waste.
// ---------------------------------------------------------------------------

#define MAXN 200000
#define MAXE 6400000
#define MAXCHUNK 64
#define NBIN 256

__device__ int   g_cnt[MAXN];
__device__ int   g_cur[MAXN];
__device__ float g_dinv[MAXN];
__device__ int   g_off[MAXN + 1];
__device__ int   g_csr[MAXE];
__device__ int   g_bsums[MAXCHUNK];
__device__ int   g_hist[NBIN];
__device__ int   g_hcur[NBIN];
__device__ int   g_hoff[NBIN];
__device__ int   g_perm[MAXN];    // sorted order -> node id
__device__ int   g_pstart[MAXN];  // CSR start, permuted
__device__ int   g_plen[MAXN];    // degree, permuted
__device__ float g_pdinv[MAXN];   // dinv, permuted
__device__ float g_bufA[(size_t)MAXN * 32];
__device__ float g_bufB[(size_t)MAXN * 16];

// ---------------- vector helpers ----------------

template <int V> __device__ __forceinline__ void vld(float* d, const float* p);
template <> __device__ __forceinline__ void vld<4>(float* d, const float* p) {
    float4 t = *reinterpret_cast<const float4*>(p);
    d[0] = t.x; d[1] = t.y; d[2] = t.z; d[3] = t.w;
}
template <> __device__ __forceinline__ void vld<2>(float* d, const float* p) {
    float2 t = *reinterpret_cast<const float2*>(p);
    d[0] = t.x; d[1] = t.y;
}
template <int V> __device__ __forceinline__ void vst(float* p, const float* d);
template <> __device__ __forceinline__ void vst<4>(float* p, const float* d) {
    *reinterpret_cast<float4*>(p) = make_float4(d[0], d[1], d[2], d[3]);
}
template <> __device__ __forceinline__ void vst<2>(float* p, const float* d) {
    *reinterpret_cast<float2*>(p) = make_float2(d[0], d[1]);
}

// ---------------- preprocessing ----------------

__global__ void k_init(int n, int nchunks) {
    int i = blockIdx.x * blockDim.x + threadIdx.x;
    if (i < n) { g_cnt[i] = 0; g_cur[i] = 0; }
    if (i < nchunks) g_bsums[i] = 0;
    if (i < NBIN) { g_hist[i] = 0; g_hcur[i] = 0; }
}

__global__ void k_count(const int* __restrict__ col, int e) {
    int i = blockIdx.x * blockDim.x + threadIdx.x;
    if (i < e) atomicAdd(&g_cnt[col[i]], 1);
}

// per-4096-chunk sums + dinv + degree histogram (fused)
__global__ void k_scan1(int n) {
    int i = blockIdx.x * blockDim.x + threadIdx.x;
    int v = 0;
    if (i < n) {
        v = g_cnt[i];
        g_dinv[i] = rsqrtf((float)v + 1.0f);
        atomicAdd(&g_hist[v < NBIN ? v : NBIN - 1], 1);
    }
    #pragma unroll
    for (int o = 16; o; o >>= 1) v += __shfl_down_sync(0xffffffffu, v, o);
    if ((threadIdx.x & 31) == 0) atomicAdd(&g_bsums[blockIdx.x >> 2], v);
}

// per-chunk exclusive scan; chunk base computed in-block from g_bsums
__global__ void k_scan3(int n, int nchunks) {
    __shared__ int wsum[32];
    __shared__ int s_base;
    if (threadIdx.x < 32) {
        int l = threadIdx.x;
        int a = (l < nchunks) ? g_bsums[l] : 0;
        int b = (l + 32 < nchunks) ? g_bsums[l + 32] : 0;
        int pre = ((l < (int)blockIdx.x) ? a : 0) + ((l + 32 < (int)blockIdx.x) ? b : 0);
        int tot = a + b;
        #pragma unroll
        for (int o = 16; o; o >>= 1) {
            pre += __shfl_down_sync(0xffffffffu, pre, o);
            tot += __shfl_down_sync(0xffffffffu, tot, o);
        }
        if (l == 0) {
            s_base = pre;
            if (blockIdx.x == gridDim.x - 1) g_off[n] = tot;
        }
    }
    int base = blockIdx.x * 4096 + threadIdx.x * 4;
    int v[4]; int s = 0;
    #pragma unroll
    for (int j = 0; j < 4; j++) { int idx = base + j; v[j] = (idx < n) ? g_cnt[idx] : 0; s += v[j]; }
    int lane = threadIdx.x & 31, w = threadIdx.x >> 5;
    int inc = s;
    #pragma unroll
    for (int o = 1; o < 32; o <<= 1) { int t = __shfl_up_sync(0xffffffffu, inc, o); if (lane >= o) inc += t; }
    if (lane == 31) wsum[w] = inc;
    __syncthreads();
    if (w == 0) {
        int ws = wsum[lane];
        #pragma unroll
        for (int o = 1; o < 32; o <<= 1) { int t = __shfl_up_sync(0xffffffffu, ws, o); if (lane >= o) ws += t; }
        wsum[lane] = ws;
    }
    __syncthreads();
    int ex = inc - s + (w ? wsum[w - 1] : 0) + s_base;
    #pragma unroll
    for (int j = 0; j < 4; j++) { int idx = base + j; if (idx < n) g_off[idx] = ex; ex += v[j]; }
}

// exclusive scan of degree histogram (1 block of 256)
__global__ void k_hscan() {
    __shared__ int ws[8];
    int l = threadIdx.x;
    int v = g_hist[l];
    int lane = l & 31, w = l >> 5;
    int inc = v;
    #pragma unroll
    for (int o = 1; o < 32; o <<= 1) { int t = __shfl_up_sync(0xffffffffu, inc, o); if (lane >= o) inc += t; }
    if (lane == 31) ws[w] = inc;
    __syncthreads();
    if (l == 0) {
        int s = 0;
        #pragma unroll
        for (int i = 0; i < 8; i++) { int t = ws[i]; ws[i] = s; s += t; }
    }
    __syncthreads();
    g_hoff[l] = inc - v + ws[w];
}

__global__ void k_fill(const int* __restrict__ row, const int* __restrict__ col, int e) {
    int i = blockIdx.x * blockDim.x + threadIdx.x;
    if (i >= e) return;
    int c = col[i];
    int p = g_off[c] + atomicAdd(&g_cur[c], 1);
    g_csr[p] = row[i];
}

// counting-sort scatter: build permuted node metadata
__global__ void k_scatter(int n) {
    int i = blockIdx.x * blockDim.x + threadIdx.x;
    if (i >= n) return;
    int c = g_cnt[i];
    int b = c < NBIN ? c : NBIN - 1;
    int pos = g_hoff[b] + atomicAdd(&g_hcur[b], 1);
    g_perm[pos]   = i;
    g_pstart[pos] = g_off[i];
    g_plen[pos]   = c;
    g_pdinv[pos]  = g_dinv[i];
}

// ---------------- layer 1 GEMM:  y1 = dinv ⊙ (x @ W1), pad-32 out -----------

__global__ void k_gemm1(const float* __restrict__ x, const float* __restrict__ W, int n) {
    __shared__ float Ws[128 * 24];
    for (int i = threadIdx.x; i < 128 * 24; i += blockDim.x) Ws[i] = W[i];
    __syncthreads();
    int r = blockIdx.x * blockDim.x + threadIdx.x;
    if (r >= n) return;
    const float4* s4 = reinterpret_cast<const float4*>(x + (size_t)r * 128);
    float acc[24];
    #pragma unroll
    for (int j = 0; j < 24; j++) acc[j] = 0.f;
    #pragma unroll 4
    for (int k4 = 0; k4 < 32; k4++) {
        float4 xv = s4[k4];
        #pragma unroll
        for (int j = 0; j < 24; j++)
            acc[j] += xv.x * Ws[(4 * k4 + 0) * 24 + j]
                    + xv.y * Ws[(4 * k4 + 1) * 24 + j]
                    + xv.z * Ws[(4 * k4 + 2) * 24 + j]
                    + xv.w * Ws[(4 * k4 + 3) * 24 + j];
    }
    float dv = g_dinv[r];
    #pragma unroll
    for (int j = 0; j < 24; j++) g_bufA[(size_t)r * 32 + j] = dv * acc[j];
}

// ---------------- fused aggregation + next-layer GEMM -----------------------
// G lanes per node (degree-sorted order); lane g owns features [g*V, g*V+V).

template <int D, int V, int G, int PIN, int DOUT, int VOUT, int POUT>
__global__ void k_aggv(const float* __restrict__ yin, float* __restrict__ yout,
                       const float* __restrict__ bias, const float* __restrict__ Wn, int n) {
    constexpr int ACT = D / V;
    constexpr int OACT = DOUT / VOUT;
    __shared__ float Ws[D * DOUT];
    for (int i = threadIdx.x; i < D * DOUT; i += blockDim.x) Ws[i] = Wn[i];
    __syncthreads();
    int t = blockIdx.x * blockDim.x + threadIdx.x;
    int idx = (G == 1) ? t : (t / G);
    int g = (G == 1) ? 0 : (t & (G - 1));
    bool valid = idx < n;
    if (!valid) idx = n - 1;
    bool active = (G == 1) || (g < ACT);
    int lane = threadIdx.x & 31;
    unsigned gmask = (G == 32) ? 0xffffffffu : (((1u << G) - 1u) << (lane & ~(G - 1)));

    int node = g_perm[idx];
    int s = g_pstart[idx];
    int e = s + g_plen[idx];
    float m[V];
    #pragma unroll
    for (int c = 0; c < V; c++) m[c] = 0.f;
    if (active) vld<V>(m, yin + (size_t)node * PIN + g * V);   // self loop

    int i = s;
    for (; i + 4 <= e; i += 4) {
        int r0 = g_csr[i], r1 = g_csr[i + 1], r2 = g_csr[i + 2], r3 = g_csr[i + 3];
        if (active) {
            float a[V], b[V], c2[V], d[V];
            vld<V>(a,  yin + (size_t)r0 * PIN + g * V);
            vld<V>(b,  yin + (size_t)r1 * PIN + g * V);
            vld<V>(c2, yin + (size_t)r2 * PIN + g * V);
            vld<V>(d,  yin + (size_t)r3 * PIN + g * V);
            #pragma unroll
            for (int c = 0; c < V; c++)
                m[c] = fmaxf(m[c], fmaxf(fmaxf(a[c], b[c]), fmaxf(c2[c], d[c])));
        }
    }
    for (; i < e; i++) {
        int r = g_csr[i];
        if (active) {
            float a[V];
            vld<V>(a, yin + (size_t)r * PIN + g * V);
            #pragma unroll
            for (int c = 0; c < V; c++) m[c] = fmaxf(m[c], a[c]);
        }
    }

    float dv = g_pdinv[idx];
    float h[V];
    #pragma unroll
    for (int c = 0; c < V; c++) {
        float bv = active ? bias[g * V + c] : 0.f;
        h[c] = tanhf(dv * m[c] + bv);
    }

    float acc[VOUT];
    #pragma unroll
    for (int v = 0; v < VOUT; v++) acc[v] = 0.f;

    if constexpr (G == 1) {
        #pragma unroll
        for (int k = 0; k < D; k++)
            #pragma unroll
            for (int v = 0; v < VOUT; v++) acc[v] += h[k] * Ws[k * DOUT + v];
    } else {
        #pragma unroll
        for (int src = 0; src < ACT; src++) {
            #pragma unroll
            for (int c = 0; c < V; c++) {
                float hk = __shfl_sync(gmask, h[c], src, G);
                if (g < OACT) {
                    #pragma unroll
                    for (int v = 0; v < VOUT; v++)
                        acc[v] += hk * Ws[(src * V + c) * DOUT + g * VOUT + v];
                }
            }
        }
    }
    if (valid && ((G == 1) || g < OACT)) {
        float outv[VOUT];
        #pragma unroll
        for (int v = 0; v < VOUT; v++) outv[v] = dv * acc[v];
        vst<VOUT>(yout + (size_t)node * POUT + g * VOUT, outv);
    }
}

// Final layer: D=2, one lane per node (degree-sorted), classifier epilogue.
__global__ void k_agg_fin(const float* __restrict__ yin, const float* __restrict__ bias,
                          const float* __restrict__ Wc, const float* __restrict__ bc,
                          float* __restrict__ out, int n, int write_h) {
    int idx = blockIdx.x * blockDim.x + threadIdx.x;
    if (idx >= n) return;
    int node = g_perm[idx];
    int s = g_pstart[idx];
    int e = s + g_plen[idx];
    float2 m = *reinterpret_cast<const float2*>(yin + (size_t)node * 2);
    int i = s;
    for (; i + 4 <= e; i += 4) {
        int r0 = g_csr[i], r1 = g_csr[i + 1], r2 = g_csr[i + 2], r3 = g_csr[i + 3];
        float2 a  = *reinterpret_cast<const float2*>(yin + (size_t)r0 * 2);
        float2 b  = *reinterpret_cast<const float2*>(yin + (size_t)r1 * 2);
        float2 c2 = *reinterpret_cast<const float2*>(yin + (size_t)r2 * 2);
        float2 d  = *reinterpret_cast<const float2*>(yin + (size_t)r3 * 2);
        m.x = fmaxf(m.x, fmaxf(fmaxf(a.x, b.x), fmaxf(c2.x, d.x)));
        m.y = fmaxf(m.y, fmaxf(fmaxf(a.y, b.y), fmaxf(c2.y, d.y)));
    }
    for (; i < e; i++) {
        int r = g_csr[i];
        float2 a = *reinterpret_cast<const float2*>(yin + (size_t)r * 2);
        m.x = fmaxf(m.x, a.x);
        m.y = fmaxf(m.y, a.y);
    }
    float dv = g_pdinv[idx];
    float h0 = tanhf(dv * m.x + bias[0]);
    float h1 = tanhf(dv * m.y + bias[1]);
    float4 o;
    o.x = h0 * Wc[0] + h1 * Wc[4] + bc[0];
    o.y = h0 * Wc[1] + h1 * Wc[5] + bc[1];
    o.z = h0 * Wc[2] + h1 * Wc[6] + bc[2];
    o.w = h0 * Wc[3] + h1 * Wc[7] + bc[3];
    reinterpret_cast<float4*>(out)[node] = o;
    if (write_h)
        reinterpret_cast<float2*>(out + (size_t)4 * n)[node] = make_float2(h0, h1);
}

// ---------------- launch ----------------

extern "C" void kernel_launch(void* const* d_in, const int* in_sizes, int n_in,
                              void* d_out, int out_size) {
    const float* x  = (const float*)d_in[0];
    const int*   ei = (const int*)d_in[1];
    const float* W1 = (const float*)d_in[2];  const float* b1 = (const float*)d_in[3];
    const float* W2 = (const float*)d_in[4];  const float* b2 = (const float*)d_in[5];
    const float* W3 = (const float*)d_in[6];  const float* b3 = (const float*)d_in[7];
    const float* W4 = (const float*)d_in[8];  const float* b4 = (const float*)d_in[9];
    const float* W5 = (const float*)d_in[10]; const float* b5 = (const float*)d_in[11];
    const float* Wc = (const float*)d_in[12]; const float* bc = (const float*)d_in[13];

    int n = in_sizes[0] / 128;
    int e = in_sizes[1] / 2;
    const int* row = ei;
    const int* col = ei + e;

    const int TB = 256;
    int nchunks = (n + 4095) / 4096;

    float* bufA = nullptr; float* bufB = nullptr;
    cudaGetSymbolAddress((void**)&bufA, g_bufA);
    cudaGetSymbolAddress((void**)&bufB, g_bufB);

    k_init   <<<(n + TB - 1) / TB, TB>>>(n, nchunks);
    k_count  <<<(e + TB - 1) / TB, TB>>>(col, e);
    k_scan1  <<<(n + 1023) / 1024, 1024>>>(n);
    k_scan3  <<<nchunks, 1024>>>(n, nchunks);
    k_hscan  <<<1, NBIN>>>();
    k_fill   <<<(e + TB - 1) / TB, TB>>>(row, col, e);
    k_scatter<<<(n + TB - 1) / TB, TB>>>(n);

    k_gemm1<<<(n + TB - 1) / TB, TB>>>(x, W1, n);   // -> bufA (pad 32)

    // <D, V, G, PIN, DOUT, VOUT, POUT>
    k_aggv<24, 4, 8, 32, 12, 4, 16><<<((size_t)n * 8 + TB - 1) / TB, TB>>>(bufA, bufB, b1, W2, n);
    k_aggv<12, 4, 4, 16,  6, 2,  8><<<((size_t)n * 4 + TB - 1) / TB, TB>>>(bufB, bufA, b2, W3, n);
    k_aggv< 6, 2, 4,  8,  4, 4,  4><<<((size_t)n * 4 + TB - 1) / TB, TB>>>(bufA, bufB, b3, W4, n);
    k_aggv< 4, 4, 1,  4,  2, 2,  2><<<((size_t)n     + TB - 1) / TB, TB>>>(bufB, bufA, b4, W5, n);

    int write_h = (out_size >= 6 * n) ? 1 : 0;
    k_agg_fin<<<(n + TB - 1) / TB, TB>>>(bufA, b5, Wc, bc, (float*)d_out, n, write_h);
}

// round 6
// speedup vs baseline: 1.2663x; 1.2663x over previous
#include <cuda_runtime.h>

// ---------------------------------------------------------------------------
// GCN 5-layer forward, max-aggregation (GB300).
//  y_l = dinv ⊙ (h_{l-1} @ W_l)  (pow2-padded rows)
//  h_l[c] = tanh( dinv[c] * max(y_l[c], y_l[nbrs]) + b_l )
//  Aggregation: lanes own float4/float2 feature chunks, natural node order
//  (locality!), unroll-8 gather loop for MLP; next-layer GEMM fused into the
//  epilogue. gemm1 uses packed fma.rn.f32x2.
// ---------------------------------------------------------------------------

#define MAXN 200000
#define MAXE 6400000
#define MAXCHUNK 64

__device__ int   g_cnt[MAXN];
__device__ int   g_cur[MAXN];
__device__ float g_dinv[MAXN];
__device__ int   g_off[MAXN + 1];
__device__ int   g_csr[MAXE];
__device__ int   g_bsums[MAXCHUNK];
__device__ float g_bufA[(size_t)MAXN * 32];
__device__ float g_bufB[(size_t)MAXN * 16];

// ---------------- vector helpers ----------------

template <int V> __device__ __forceinline__ void vld(float* d, const float* p);
template <> __device__ __forceinline__ void vld<4>(float* d, const float* p) {
    float4 t = *reinterpret_cast<const float4*>(p);
    d[0] = t.x; d[1] = t.y; d[2] = t.z; d[3] = t.w;
}
template <> __device__ __forceinline__ void vld<2>(float* d, const float* p) {
    float2 t = *reinterpret_cast<const float2*>(p);
    d[0] = t.x; d[1] = t.y;
}
template <int V> __device__ __forceinline__ void vst(float* p, const float* d);
template <> __device__ __forceinline__ void vst<4>(float* p, const float* d) {
    *reinterpret_cast<float4*>(p) = make_float4(d[0], d[1], d[2], d[3]);
}
template <> __device__ __forceinline__ void vst<2>(float* p, const float* d) {
    *reinterpret_cast<float2*>(p) = make_float2(d[0], d[1]);
}

// ---------------- preprocessing ----------------

__global__ void k_init(int n, int nchunks) {
    int i = blockIdx.x * blockDim.x + threadIdx.x;
    if (i < n) { g_cnt[i] = 0; g_cur[i] = 0; }
    if (i < nchunks) g_bsums[i] = 0;
}

__global__ void k_count(const int* __restrict__ col, int e) {
    int i = blockIdx.x * blockDim.x + threadIdx.x;
    if (i < e) atomicAdd(&g_cnt[col[i]], 1);
}

__global__ void k_scan1(int n) {
    int i = blockIdx.x * blockDim.x + threadIdx.x;
    int v = 0;
    if (i < n) { v = g_cnt[i]; g_dinv[i] = rsqrtf((float)v + 1.0f); }
    #pragma unroll
    for (int o = 16; o; o >>= 1) v += __shfl_down_sync(0xffffffffu, v, o);
    if ((threadIdx.x & 31) == 0) atomicAdd(&g_bsums[blockIdx.x >> 2], v);
}

__global__ void k_scan3(int n, int nchunks) {
    __shared__ int wsum[32];
    __shared__ int s_base;
    if (threadIdx.x < 32) {
        int l = threadIdx.x;
        int a = (l < nchunks) ? g_bsums[l] : 0;
        int b = (l + 32 < nchunks) ? g_bsums[l + 32] : 0;
        int pre = ((l < (int)blockIdx.x) ? a : 0) + ((l + 32 < (int)blockIdx.x) ? b : 0);
        int tot = a + b;
        #pragma unroll
        for (int o = 16; o; o >>= 1) {
            pre += __shfl_down_sync(0xffffffffu, pre, o);
            tot += __shfl_down_sync(0xffffffffu, tot, o);
        }
        if (l == 0) {
            s_base = pre;
            if (blockIdx.x == gridDim.x - 1) g_off[n] = tot;
        }
    }
    int base = blockIdx.x * 4096 + threadIdx.x * 4;
    int v[4]; int s = 0;
    #pragma unroll
    for (int j = 0; j < 4; j++) { int idx = base + j; v[j] = (idx < n) ? g_cnt[idx] : 0; s += v[j]; }
    int lane = threadIdx.x & 31, w = threadIdx.x >> 5;
    int inc = s;
    #pragma unroll
    for (int o = 1; o < 32; o <<= 1) { int t = __shfl_up_sync(0xffffffffu, inc, o); if (lane >= o) inc += t; }
    if (lane == 31) wsum[w] = inc;
    __syncthreads();
    if (w == 0) {
        int ws = wsum[lane];
        #pragma unroll
        for (int o = 1; o < 32; o <<= 1) { int t = __shfl_up_sync(0xffffffffu, ws, o); if (lane >= o) ws += t; }
        wsum[lane] = ws;
    }
    __syncthreads();
    int ex = inc - s + (w ? wsum[w - 1] : 0) + s_base;
    #pragma unroll
    for (int j = 0; j < 4; j++) { int idx = base + j; if (idx < n) g_off[idx] = ex; ex += v[j]; }
}

__global__ void k_fill(const int* __restrict__ row, const int* __restrict__ col, int e) {
    int i = blockIdx.x * blockDim.x + threadIdx.x;
    if (i >= e) return;
    int c = col[i];
    int p = g_off[c] + atomicAdd(&g_cur[c], 1);
    g_csr[p] = row[i];
}

// ---------------- layer 1 GEMM:  y1 = dinv ⊙ (x @ W1), packed f32x2 ---------

__device__ __forceinline__ unsigned long long pk2(float x, float y) {
    unsigned long long r;
    asm("mov.b64 %0, {%1, %2};" : "=l"(r) : "f"(x), "f"(y));
    return r;
}
__device__ __forceinline__ void upk2(unsigned long long v, float& x, float& y) {
    asm("mov.b64 {%0, %1}, %2;" : "=f"(x), "=f"(y) : "l"(v));
}
__device__ __forceinline__ void ffma2(unsigned long long& acc, unsigned long long a,
                                      unsigned long long b) {
    asm("fma.rn.f32x2 %0, %1, %2, %3;" : "=l"(acc) : "l"(a), "l"(b), "l"(acc));
}

__global__ void __launch_bounds__(256) k_gemm1(const float* __restrict__ x,
                                               const float* __restrict__ W, int n) {
    __shared__ unsigned long long Ws[128 * 12];   // W as f32x2 pairs, row-major
    const unsigned long long* Wp = reinterpret_cast<const unsigned long long*>(W);
    for (int i = threadIdx.x; i < 128 * 12; i += blockDim.x) Ws[i] = Wp[i];
    __syncthreads();
    int r = blockIdx.x * blockDim.x + threadIdx.x;
    if (r >= n) return;
    const float4* s4 = reinterpret_cast<const float4*>(x + (size_t)r * 128);
    unsigned long long acc[12];
    #pragma unroll
    for (int j = 0; j < 12; j++) acc[j] = 0ull;  // (0.f,0.f)
    #pragma unroll 4
    for (int k4 = 0; k4 < 32; k4++) {
        float4 xv = s4[k4];
        unsigned long long a0 = pk2(xv.x, xv.x);
        unsigned long long a1 = pk2(xv.y, xv.y);
        unsigned long long a2 = pk2(xv.z, xv.z);
        unsigned long long a3 = pk2(xv.w, xv.w);
        #pragma unroll
        for (int j = 0; j < 12; j++) {
            ffma2(acc[j], a0, Ws[(4 * k4 + 0) * 12 + j]);
            ffma2(acc[j], a1, Ws[(4 * k4 + 1) * 12 + j]);
            ffma2(acc[j], a2, Ws[(4 * k4 + 2) * 12 + j]);
            ffma2(acc[j], a3, Ws[(4 * k4 + 3) * 12 + j]);
        }
    }
    float dv = g_dinv[r];
    #pragma unroll
    for (int j = 0; j < 12; j++) {
        float a, b;
        upk2(acc[j], a, b);
        g_bufA[(size_t)r * 32 + 2 * j]     = dv * a;
        g_bufA[(size_t)r * 32 + 2 * j + 1] = dv * b;
    }
}

// ---------------- fused aggregation + next-layer GEMM -----------------------
// G lanes per node; lane g owns features [g*V, g*V+V). Unroll-8 gathers.

template <int V>
__device__ __forceinline__ void vmax(float* m, const float* a) {
    #pragma unroll
    for (int c = 0; c < V; c++) m[c] = fmaxf(m[c], a[c]);
}

template <int D, int V, int G, int PIN, int DOUT, int VOUT, int POUT>
__global__ void __launch_bounds__(256) k_aggv(const float* __restrict__ yin,
                                              float* __restrict__ yout,
                                              const float* __restrict__ bias,
                                              const float* __restrict__ Wn, int n) {
    constexpr int ACT = D / V;
    constexpr int OACT = DOUT / VOUT;
    __shared__ float Ws[D * DOUT];
    for (int i = threadIdx.x; i < D * DOUT; i += blockDim.x) Ws[i] = Wn[i];
    __syncthreads();
    int t = blockIdx.x * blockDim.x + threadIdx.x;
    int node = (G == 1) ? t : (t / G);
    int g = (G == 1) ? 0 : (t & (G - 1));
    bool valid = node < n;
    if (!valid) node = n - 1;
    bool active = (G == 1) || (g < ACT);
    int lane = threadIdx.x & 31;
    unsigned gmask = (G == 32) ? 0xffffffffu : (((1u << G) - 1u) << (lane & ~(G - 1)));

    int s = g_off[node], e = g_off[node + 1];
    float m[V];
    #pragma unroll
    for (int c = 0; c < V; c++) m[c] = 0.f;
    if (active) vld<V>(m, yin + (size_t)node * PIN + g * V);   // self loop

    int i = s;
    for (; i + 8 <= e; i += 8) {
        int r0 = g_csr[i],     r1 = g_csr[i + 1], r2 = g_csr[i + 2], r3 = g_csr[i + 3];
        int r4 = g_csr[i + 4], r5 = g_csr[i + 5], r6 = g_csr[i + 6], r7 = g_csr[i + 7];
        if (active) {
            float a0[V], a1[V], a2[V], a3[V], a4[V], a5[V], a6[V], a7[V];
            vld<V>(a0, yin + (size_t)r0 * PIN + g * V);
            vld<V>(a1, yin + (size_t)r1 * PIN + g * V);
            vld<V>(a2, yin + (size_t)r2 * PIN + g * V);
            vld<V>(a3, yin + (size_t)r3 * PIN + g * V);
            vld<V>(a4, yin + (size_t)r4 * PIN + g * V);
            vld<V>(a5, yin + (size_t)r5 * PIN + g * V);
            vld<V>(a6, yin + (size_t)r6 * PIN + g * V);
            vld<V>(a7, yin + (size_t)r7 * PIN + g * V);
            vmax<V>(m, a0); vmax<V>(m, a1); vmax<V>(m, a2); vmax<V>(m, a3);
            vmax<V>(m, a4); vmax<V>(m, a5); vmax<V>(m, a6); vmax<V>(m, a7);
        }
    }
    for (; i + 2 <= e; i += 2) {
        int r0 = g_csr[i], r1 = g_csr[i + 1];
        if (active) {
            float a0[V], a1[V];
            vld<V>(a0, yin + (size_t)r0 * PIN + g * V);
            vld<V>(a1, yin + (size_t)r1 * PIN + g * V);
            vmax<V>(m, a0); vmax<V>(m, a1);
        }
    }
    if (i < e) {
        int r0 = g_csr[i];
        if (active) {
            float a0[V];
            vld<V>(a0, yin + (size_t)r0 * PIN + g * V);
            vmax<V>(m, a0);
        }
    }

    float dv = g_dinv[node];
    float h[V];
    #pragma unroll
    for (int c = 0; c < V; c++) {
        float bv = active ? bias[g * V + c] : 0.f;
        h[c] = tanhf(dv * m[c] + bv);
    }

    float acc[VOUT];
    #pragma unroll
    for (int v = 0; v < VOUT; v++) acc[v] = 0.f;

    if constexpr (G == 1) {
        #pragma unroll
        for (int k = 0; k < D; k++)
            #pragma unroll
            for (int v = 0; v < VOUT; v++) acc[v] += h[k] * Ws[k * DOUT + v];
    } else {
        #pragma unroll
        for (int src = 0; src < ACT; src++) {
            #pragma unroll
            for (int c = 0; c < V; c++) {
                float hk = __shfl_sync(gmask, h[c], src, G);
                if (g < OACT) {
                    #pragma unroll
                    for (int v = 0; v < VOUT; v++)
                        acc[v] += hk * Ws[(src * V + c) * DOUT + g * VOUT + v];
                }
            }
        }
    }
    if (valid && ((G == 1) || g < OACT)) {
        float outv[VOUT];
        #pragma unroll
        for (int v = 0; v < VOUT; v++) outv[v] = dv * acc[v];
        vst<VOUT>(yout + (size_t)node * POUT + g * VOUT, outv);
    }
}

// Final layer: D=2, one lane per node, classifier epilogue. Unroll-8.
__global__ void __launch_bounds__(256) k_agg_fin(const float* __restrict__ yin,
                                                 const float* __restrict__ bias,
                                                 const float* __restrict__ Wc,
                                                 const float* __restrict__ bc,
                                                 float* __restrict__ out, int n, int write_h) {
    int node = blockIdx.x * blockDim.x + threadIdx.x;
    if (node >= n) return;
    int s = g_off[node], e = g_off[node + 1];
    float2 m = *reinterpret_cast<const float2*>(yin + (size_t)node * 2);
    int i = s;
    for (; i + 8 <= e; i += 8) {
        int r0 = g_csr[i],     r1 = g_csr[i + 1], r2 = g_csr[i + 2], r3 = g_csr[i + 3];
        int r4 = g_csr[i + 4], r5 = g_csr[i + 5], r6 = g_csr[i + 6], r7 = g_csr[i + 7];
        float2 a0 = *reinterpret_cast<const float2*>(yin + (size_t)r0 * 2);
        float2 a1 = *reinterpret_cast<const float2*>(yin + (size_t)r1 * 2);
        float2 a2 = *reinterpret_cast<const float2*>(yin + (size_t)r2 * 2);
        float2 a3 = *reinterpret_cast<const float2*>(yin + (size_t)r3 * 2);
        float2 a4 = *reinterpret_cast<const float2*>(yin + (size_t)r4 * 2);
        float2 a5 = *reinterpret_cast<const float2*>(yin + (size_t)r5 * 2);
        float2 a6 = *reinterpret_cast<const float2*>(yin + (size_t)r6 * 2);
        float2 a7 = *reinterpret_cast<const float2*>(yin + (size_t)r7 * 2);
        m.x = fmaxf(m.x, fmaxf(fmaxf(a0.x, a1.x), fmaxf(a2.x, a3.x)));
        m.x = fmaxf(m.x, fmaxf(fmaxf(a4.x, a5.x), fmaxf(a6.x, a7.x)));
        m.y = fmaxf(m.y, fmaxf(fmaxf(a0.y, a1.y), fmaxf(a2.y, a3.y)));
        m.y = fmaxf(m.y, fmaxf(fmaxf(a4.y, a5.y), fmaxf(a6.y, a7.y)));
    }
    for (; i < e; i++) {
        int r = g_csr[i];
        float2 a = *reinterpret_cast<const float2*>(yin + (size_t)r * 2);
        m.x = fmaxf(m.x, a.x);
        m.y = fmaxf(m.y, a.y);
    }
    float dv = g_dinv[node];
    float h0 = tanhf(dv * m.x + bias[0]);
    float h1 = tanhf(dv * m.y + bias[1]);
    float4 o;
    o.x = h0 * Wc[0] + h1 * Wc[4] + bc[0];
    o.y = h0 * Wc[1] + h1 * Wc[5] + bc[1];
    o.z = h0 * Wc[2] + h1 * Wc[6] + bc[2];
    o.w = h0 * Wc[3] + h1 * Wc[7] + bc[3];
    reinterpret_cast<float4*>(out)[node] = o;
    if (write_h)
        reinterpret_cast<float2*>(out + (size_t)4 * n)[node] = make_float2(h0, h1);
}

// ---------------- launch ----------------

extern "C" void kernel_launch(void* const* d_in, const int* in_sizes, int n_in,
                              void* d_out, int out_size) {
    const float* x  = (const float*)d_in[0];
    const int*   ei = (const int*)d_in[1];
    const float* W1 = (const float*)d_in[2];  const float* b1 = (const float*)d_in[3];
    const float* W2 = (const float*)d_in[4];  const float* b2 = (const float*)d_in[5];
    const float* W3 = (const float*)d_in[6];  const float* b3 = (const float*)d_in[7];
    const float* W4 = (const float*)d_in[8];  const float* b4 = (const float*)d_in[9];
    const float* W5 = (const float*)d_in[10]; const float* b5 = (const float*)d_in[11];
    const float* Wc = (const float*)d_in[12]; const float* bc = (const float*)d_in[13];

    int n = in_sizes[0] / 128;
    int e = in_sizes[1] / 2;
    const int* row = ei;
    const int* col = ei + e;

    const int TB = 256;
    int nchunks = (n + 4095) / 4096;

    float* bufA = nullptr; float* bufB = nullptr;
    cudaGetSymbolAddress((void**)&bufA, g_bufA);
    cudaGetSymbolAddress((void**)&bufB, g_bufB);

    k_init <<<(n + TB - 1) / TB, TB>>>(n, nchunks);
    k_count<<<(e + TB - 1) / TB, TB>>>(col, e);
    k_scan1<<<(n + 1023) / 1024, 1024>>>(n);
    k_scan3<<<nchunks, 1024>>>(n, nchunks);
    k_fill <<<(e + TB - 1) / TB, TB>>>(row, col, e);

    k_gemm1<<<(n + TB - 1) / TB, TB>>>(x, W1, n);   // -> bufA (pad 32)

    // <D, V, G, PIN, DOUT, VOUT, POUT>
    k_aggv<24, 4, 8, 32, 12, 4, 16><<<((size_t)n * 8 + TB - 1) / TB, TB>>>(bufA, bufB, b1, W2, n);
    k_aggv<12, 4, 4, 16,  6, 2,  8><<<((size_t)n * 4 + TB - 1) / TB, TB>>>(bufB, bufA, b2, W3, n);
    k_aggv< 6, 2, 4,  8,  4, 4,  4><<<((size_t)n * 4 + TB - 1) / TB, TB>>>(bufA, bufB, b3, W4, n);
    k_aggv< 4, 4, 1,  4,  2, 2,  2><<<((size_t)n     + TB - 1) / TB, TB>>>(bufB, bufA, b4, W5, n);

    int write_h = (out_size >= 6 * n) ? 1 : 0;
    k_agg_fin<<<(n + TB - 1) / TB, TB>>>(bufA, b5, Wc, bc, (float*)d_out, n, write_h);
}